// round 1
// baseline (speedup 1.0000x reference)
#include <cuda_runtime.h>

#define TI 16
#define TC 64
#define RR (2*TI+7)      // 39 raw rows in tile
#define CC (2*TC+7)      // 135 raw cols in tile
#define CPAD 136
#define NN 1024
#define HH 512
#define NTHREADS 256

__global__ __launch_bounds__(NTHREADS)
void ilwt2d_fused_kernel(const float* __restrict__ x, float* __restrict__ out) {
    // tile is reused for Dcol buffers after the row transform (it is dead then)
    __shared__ float tile[RR * CPAD];          // 5304 floats
    __shared__ float sArr[RR * TC];            // s[r][j], j -> col c0+j
    __shared__ float dArr[RR * (TC + 2)];      // d[r][k], k -> col refl(c0-1+k)

    const int tid = threadIdx.x;
    const int c0 = blockIdx.x * TC;
    const int i0 = blockIdx.y * TI;
    const int img = blockIdx.z;                // b*3 + ch
    const int cbase = 2 * c0 - 4;
    const int rbase = 2 * i0 - 4;
    const float* __restrict__ xp = x + (size_t)img * NN * NN;

    // ---- 1. load input halo tile (clamped; clamped values are never read:
    //         boundary handling is index-reflection in the half-index domain) ----
    for (int idx = tid; idx < RR * CC; idx += NTHREADS) {
        int r = idx / CC, cc = idx - r * CC;
        int rr = rbase + r; rr = max(0, min(NN - 1, rr));
        int rc = cbase + cc; rc = max(0, min(NN - 1, rc));
        tile[r * CPAD + cc] = xp[(size_t)rr * NN + rc];
    }
    __syncthreads();

    // ---- 2. row lift, detail: dArr[r][k] = d[refl(c0-1+k)] ----
    for (int idx = tid; idx < RR * (TC + 2); idx += NTHREADS) {
        int r = idx / (TC + 2), k = idx - r * (TC + 2);
        int c = c0 - 1 + k;
        if (c < 0) c = -c;
        if (c > HH - 1) c = 2 * (HH - 1) - c;
        int cm = c - 1, cp = c + 1;
        if (cm < 0) cm = -cm;
        if (cp > HH - 1) cp = 2 * (HH - 1) - cp;
        const float* tr = tile + r * CPAD;
        dArr[idx] = tr[2 * c + 1 - cbase]
                  - 0.5f * (tr[2 * cm - cbase] + tr[2 * cp - cbase]);
    }
    __syncthreads();

    // ---- 3. row lift, smooth: sArr[r][j] = s[c0+j] ----
    for (int idx = tid; idx < RR * TC; idx += NTHREADS) {
        int r = idx / TC, j = idx - r * TC;
        int c = c0 + j;
        sArr[idx] = tile[r * CPAD + 2 * c - cbase]
                  + 0.25f * (dArr[r * (TC + 2) + j] + dArr[r * (TC + 2) + j + 2]);
    }
    __syncthreads();

    // ---- 4. column lift, detail (Dcol buffers alias the dead input tile) ----
    float* DcolS = tile;                       // (TI+2)*TC floats
    float* DcolD = tile + (TI + 2) * TC;       // (TI+2)*TC floats
    for (int idx = tid; idx < (TI + 2) * TC; idx += NTHREADS) {
        int t = idx / TC, j = idx - t * TC;
        int i = i0 - 1 + t;
        if (i < 0) i = -i;
        if (i > HH - 1) i = 2 * (HH - 1) - i;
        int im = i - 1, ip = i + 1;
        if (im < 0) im = -im;
        if (ip > HH - 1) ip = 2 * (HH - 1) - ip;
        int ro = 2 * i + 1 - rbase;            // odd row (tile index)
        int rm = 2 * im - rbase;               // even row i-1
        int rp = 2 * ip - rbase;               // even row i+1
        DcolS[idx] = sArr[ro * TC + j]
                   - 0.5f * (sArr[rm * TC + j] + sArr[rp * TC + j]);
        DcolD[idx] = dArr[ro * (TC + 2) + j + 1]
                   - 0.5f * (dArr[rm * (TC + 2) + j + 1] + dArr[rp * (TC + 2) + j + 1]);
    }
    __syncthreads();

    // ---- 5. column lift, smooth + write all 4 subbands ----
    const int b = img / 3, ch = img - 3 * b;
    const size_t plane = (size_t)HH * HH;
    float* __restrict__ outb = out + (size_t)b * 12 * plane + (size_t)ch * plane;

    for (int idx = tid; idx < TI * TC; idx += NTHREADS) {
        int t0 = idx / TC, j = idx - t0 * TC;
        int t = t0 + 1;
        int i = i0 + t0, c = c0 + j;
        int re = 2 * t0 + 4;                   // tile row of even input row 2i
        float vLL = sArr[re * TC + j]
                  + 0.25f * (DcolS[(t - 1) * TC + j] + DcolS[(t + 1) * TC + j]);
        float vLH = DcolS[t * TC + j];
        float vHL = dArr[re * (TC + 2) + j + 1]
                  + 0.25f * (DcolD[(t - 1) * TC + j] + DcolD[(t + 1) * TC + j]);
        float vHH = DcolD[t * TC + j];
        size_t oidx = (size_t)i * HH + c;
        outb[oidx] = vLL;
        outb[3 * plane + oidx] = vLH;
        outb[6 * plane + oidx] = vHL;
        outb[9 * plane + oidx] = vHH;
    }
}

extern "C" void kernel_launch(void* const* d_in, const int* in_sizes, int n_in,
                              void* d_out, int out_size) {
    const float* x = (const float*)d_in[0];
    float* out = (float*)d_out;
    dim3 grid(HH / TC, HH / TI, 24);   // 8 x 32 x 24
    ilwt2d_fused_kernel<<<grid, NTHREADS>>>(x, out);
}

// round 2
// speedup vs baseline: 1.5602x; 1.5602x over previous
#include <cuda_runtime.h>

#define NN 1024
#define HH 512
#define TI 32            // output rows per CTA chunk
#define WCOLS 64         // output cols per warp
#define NWARPS 8
#define NTHREADS (NWARPS*32)

__device__ __forceinline__ int reflC(int c) {
    if (c < 0) c = -c;
    if (c > HH - 1) c = 2 * (HH - 1) - c;
    return c;
}

struct V4 { float s0, s1, d0, d1; };

// Row lift of raw row pointer rp for this lane's 2 output columns.
// haloA/haloB are precomputed reflected halo float-offsets (valid on lanes 0,31).
__device__ __forceinline__ V4 rowlift(const float* __restrict__ rp,
                                      int lane, bool edge,
                                      int haloA, int haloB, int loff) {
    float4 v = *reinterpret_cast<const float4*>(rp + loff);
    float evenA = 0.f, oddA = 0.f, evenB = 0.f;
    if (edge) {                                   // predicated, lanes 0 & 31 only
        float2 ha = *reinterpret_cast<const float2*>(rp + haloA);
        evenA = ha.x; oddA = ha.y;
        evenB = rp[haloB];
    }
    // even-neighbor exchange
    float eL = __shfl_up_sync(0xffffffffu, v.z, 1);   // even[2j-1]
    if (lane == 0)  eL = evenA;
    float eR = __shfl_down_sync(0xffffffffu, v.x, 1); // even[2j+2]
    if (lane == 31) eR = evenA;
    float d0 = v.y - 0.5f * (eL + v.z);   // d[2j]   = odd - 1/2(even[c-1]+even[c+1])
    float d1 = v.w - 0.5f * (v.x + eR);   // d[2j+1]
    // d-neighbor exchange
    float dL = __shfl_up_sync(0xffffffffu, d1, 1);    // d[2j-1]
    if (lane == 0)  dL = oddA - 0.5f * (evenB + v.x); // d[C0-1] via reflected halo
    float dR = __shfl_down_sync(0xffffffffu, d0, 1);  // d[2j+2]
    if (lane == 31) dR = oddA - 0.5f * (v.z + evenB); // d[C0+64] via reflected halo
    V4 r;
    r.d0 = d0; r.d1 = d1;
    r.s0 = v.x + 0.25f * (dL + d1);
    r.s1 = v.z + 0.25f * (d0 + dR);
    return r;
}

#define LIFT(i_half_even_or_odd_row) \
    rowlift(xp + (size_t)(i_half_even_or_odd_row) * NN, lane, edge, haloA, haloB, loff)

__global__ __launch_bounds__(NTHREADS)
void ilwt2d_warp_kernel(const float* __restrict__ x, float* __restrict__ out) {
    const int lane = threadIdx.x & 31;
    const int w = threadIdx.x >> 5;
    const int C0 = w * WCOLS;
    const int i0 = blockIdx.x * TI;
    const int img = blockIdx.y;
    const float* __restrict__ xp = x + (size_t)img * NN * NN;

    const int b = img / 3, ch = img - 3 * b;
    const size_t plane = (size_t)HH * HH;
    float* __restrict__ outb = out + (size_t)b * 12 * plane + (size_t)ch * plane;
    const int ocol = C0 + 2 * lane;

    // Precompute halo addressing (column reflection baked into addresses).
    const bool edge = (lane == 0) || (lane == 31);
    int haloA, haloB;
    if (lane == 31) {
        haloA = 2 * reflC(C0 + 64);      // {even,odd}[C0+64]
        haloB = 2 * reflC(C0 + 65);      // even[C0+65]
    } else {
        haloA = 2 * reflC(C0 - 1);       // {even,odd}[C0-1]
        haloB = 2 * reflC(C0 - 2);       // even[C0-2]
    }
    const int loff = 2 * C0 + 4 * lane;

    // -------- prologue: build column-lift pipeline state --------
    // E[i] = rowlift(raw row 2*refl(i)), O[i] = rowlift(raw row 2*refl(i)+1)
    V4 Ecur  = LIFT(2 * i0);                         // E[i0]
    V4 Em    = LIFT(2 * reflC(i0 - 1));              // E[i0-1]
    V4 Em2   = LIFT(2 * reflC(i0 - 2));              // E[i0-2]
    V4 Om1   = LIFT(2 * reflC(i0 - 1) + 1);          // O[i0-1]
    V4 Dprev;                                        // Dcol[i0-1]
    Dprev.s0 = Om1.s0 - 0.5f * (Em2.s0 + Ecur.s0);
    Dprev.s1 = Om1.s1 - 0.5f * (Em2.s1 + Ecur.s1);
    Dprev.d0 = Om1.d0 - 0.5f * (Em2.d0 + Ecur.d0);
    Dprev.d1 = Om1.d1 - 0.5f * (Em2.d1 + Ecur.d1);
    V4 Enext = LIFT(2 * reflC(i0 + 1));              // E[i0+1]
    V4 O0    = LIFT(2 * i0 + 1);                     // O[i0]
    V4 Dcur;                                         // Dcol[i0]
    Dcur.s0 = O0.s0 - 0.5f * (Em.s0 + Enext.s0);
    Dcur.s1 = O0.s1 - 0.5f * (Em.s1 + Enext.s1);
    Dcur.d0 = O0.d0 - 0.5f * (Em.d0 + Enext.d0);
    Dcur.d1 = O0.d1 - 0.5f * (Em.d1 + Enext.d1);

    // -------- main streaming loop over output rows --------
    #pragma unroll 2
    for (int t = 0; t < TI; ++t) {
        const int i = i0 + t;
        V4 En2 = LIFT(2 * reflC(i + 2));             // E[i+2]
        V4 Oi1 = LIFT(2 * reflC(i + 1) + 1);         // O[i+1]
        V4 Dnext;                                    // Dcol[i+1]
        Dnext.s0 = Oi1.s0 - 0.5f * (Ecur.s0 + En2.s0);
        Dnext.s1 = Oi1.s1 - 0.5f * (Ecur.s1 + En2.s1);
        Dnext.d0 = Oi1.d0 - 0.5f * (Ecur.d0 + En2.d0);
        Dnext.d1 = Oi1.d1 - 0.5f * (Ecur.d1 + En2.d1);

        float2 ll = { Ecur.s0 + 0.25f * (Dprev.s0 + Dnext.s0),
                      Ecur.s1 + 0.25f * (Dprev.s1 + Dnext.s1) };
        float2 lh = { Dcur.s0, Dcur.s1 };
        float2 hl = { Ecur.d0 + 0.25f * (Dprev.d0 + Dnext.d0),
                      Ecur.d1 + 0.25f * (Dprev.d1 + Dnext.d1) };
        float2 hh = { Dcur.d0, Dcur.d1 };

        const size_t o = (size_t)i * HH + ocol;
        *reinterpret_cast<float2*>(outb + o)             = ll;
        *reinterpret_cast<float2*>(outb + 3 * plane + o) = lh;
        *reinterpret_cast<float2*>(outb + 6 * plane + o) = hl;
        *reinterpret_cast<float2*>(outb + 9 * plane + o) = hh;

        Ecur = Enext; Enext = En2;
        Dprev = Dcur; Dcur = Dnext;
    }
}

extern "C" void kernel_launch(void* const* d_in, const int* in_sizes, int n_in,
                              void* d_out, int out_size) {
    const float* x = (const float*)d_in[0];
    float* out = (float*)d_out;
    dim3 grid(HH / TI, 24);   // 16 x 24 = 384 CTAs, 8 warps each
    ilwt2d_warp_kernel<<<grid, NTHREADS>>>(x, out);
}